// round 6
// baseline (speedup 1.0000x reference)
#include <cuda_runtime.h>
#include <cuda_bf16.h>
#include <math.h>

// Problem constants (fixed by the dataset)
#define B_   2
#define C_   64
#define E_   4
#define HLR_ 192
#define WLR_ 192
#define HHR_ 384
#define WHR_ 384
#define HWLR_ (HLR_*WLR_)
#define HWHR_ (HHR_*WHR_)

// ---------------------------------------------------------------------------
// Single fused kernel. Block = 512 threads = 16 warps.
// Prologue (per block, ~1us): tiny parity MLP -> routing/offset -> dynamic
//   weights mixed straight into shared memory (only this block's hp).
// Main: warp ww: g = ww & 7 (channel group of 8), half = ww >> 3.
//   lane l -> LR column m = mbase + half*32 + l; thread produces BOTH
//   w-parities (HR cols w=2m, 2m+1): shared bilinear window, shared weights,
//   contiguous float2 stores.
// grid = (WHR/128, HHR, B).
// ---------------------------------------------------------------------------
__global__ void __launch_bounds__(512, 2) upsample_fused(
    const float* __restrict__ fused, float* __restrict__ out,
    const float* __restrict__ w1, const float* __restrict__ b1,
    const float* __restrict__ w2, const float* __restrict__ b2,
    const float* __restrict__ rw, const float* __restrict__ rb,
    const float* __restrict__ ow, const float* __restrict__ ob,
    const float* __restrict__ WC, const float* __restrict__ WE)
{
    __shared__ float s_wc[2][8][64];        // [q][j][c]
    __shared__ float s_we[2][64][8];        // [q][c][j]
    __shared__ float s_part[8][8][2][64];   // [j][g][q][m]
    __shared__ float s_midf[8][2][64];      // [j][q][m]
    __shared__ float s_emb[2][64];          // parity MLP embeddings (this hp)
    __shared__ float s_rt[2][4];            // routing
    __shared__ float s_off[2][2];           // offsets
    // fast-window constants
    __shared__ int   sh_fast, sh_dy, sh_dxmin, sh_o0, sh_o1;
    __shared__ float sh_wx[2], sh_wy[2], sh_offx[2], sh_offy[2];

    const int tid  = threadIdx.x;
    const int l    = tid & 31;
    const int ww   = tid >> 5;
    const int g    = ww & 7;
    const int half = ww >> 3;
    const int h    = blockIdx.y;
    const int hp   = h & 1;
    const int byy  = h >> 1;
    const int b    = blockIdx.z;
    const int mbase = blockIdx.x * 64;
    const int ml   = half * 32 + l;          // m within tile [0,64)
    const int m    = mbase + ml;             // LR column

    // ============ Prologue: per-parity MLP (2 variants for this hp) =======
    if (tid < 128) {
        const int wp = tid >> 6;
        const int o  = tid & 63;
        float ch = (hp + 0.5f) * 0.5f; ch = ch - floorf(ch + 0.001f) - 0.5f;
        float cw = (wp + 0.5f) * 0.5f; cw = cw - floorf(cw + 0.001f) - 0.5f;
        const float inp0 = 0.5f, inp1 = 0.5f, inp2 = ch, inp3 = cw;
        float acc = b2[o];
        #pragma unroll 8
        for (int k = 0; k < 64; k++) {
            float e1 = b1[k]
                     + w1[k*4+0]*inp0 + w1[k*4+1]*inp1
                     + w1[k*4+2]*inp2 + w1[k*4+3]*inp3;
            e1 = fmaxf(e1, 0.0f);
            acc += w2[o*64 + k] * e1;
        }
        s_emb[wp][o] = fmaxf(acc, 0.0f);
    }
    __syncthreads();

    if (tid < 8) {               // routing: wp = tid>>2, e = tid&3
        const int wp = tid >> 2, e = tid & 3;
        float a = rb[e];
        #pragma unroll 8
        for (int k = 0; k < 64; k++) a += rw[e*64 + k] * s_emb[wp][k];
        s_rt[wp][e] = 1.0f / (1.0f + expf(-a));
    } else if (tid < 12) {       // offsets: wp = (tid-8)>>1, k = (tid-8)&1
        const int idx = tid - 8, wp = idx >> 1, k = idx & 1;
        float a = ob[k];
        #pragma unroll 8
        for (int j = 0; j < 64; j++) a += ow[k*64 + j] * s_emb[wp][j];
        s_off[wp][k] = a;
    }
    __syncthreads();

    // fast-window constants (one thread)
    if (tid == 0) {
        float ox0 = s_off[0][0], oy0 = s_off[0][1];
        float ox1 = s_off[1][0], oy1 = s_off[1][1];
        sh_offx[0] = ox0; sh_offx[1] = ox1;
        sh_offy[0] = oy0; sh_offy[1] = oy1;
        float tx0 = -0.25f + ox0;
        float tx1 =  0.25f + ox1;
        float tyb = (hp + 0.5f) * 0.5f - 0.5f;
        float ty0 = tyb + oy0;
        float ty1 = tyb + oy1;
        float fx0 = floorf(tx0), fx1 = floorf(tx1);
        float fy0 = floorf(ty0), fy1 = floorf(ty1);
        int dx0 = (int)fx0, dx1 = (int)fx1;
        int dy0 = (int)fy0, dy1 = (int)fy1;
        sh_fast  = (dy0 == dy1) && (abs(dx1 - dx0) <= 1);
        int dmn = min(dx0, dx1);
        sh_dy    = dy0;
        sh_dxmin = dmn;
        sh_o0    = dx0 - dmn;
        sh_o1    = dx1 - dmn;
        sh_wx[0] = tx0 - fx0;  sh_wx[1] = tx1 - fx1;
        sh_wy[0] = ty0 - fy0;  sh_wy[1] = ty1 - fy1;
    }

    // mix dynamic weights straight into shared: 2 wp x (512 wc + 512 we)
    {
        float* wcf = &s_wc[0][0][0];
        float* wef = &s_we[0][0][0];
        #pragma unroll
        for (int it = 0; it < 4; it++) {
            int idx = tid + it * 512;          // 0..2047
            int wp  = idx >> 10;
            int r   = idx & 1023;
            float r0 = s_rt[wp][0], r1 = s_rt[wp][1];
            float r2 = s_rt[wp][2], r3 = s_rt[wp][3];
            if (r < 512) {
                float a = r0 * WC[0*512 + r] + r1 * WC[1*512 + r]
                        + r2 * WC[2*512 + r] + r3 * WC[3*512 + r];
                wcf[wp * 512 + r] = a;
            } else {
                int rr = r - 512;
                float a = r0 * WE[0*512 + rr] + r1 * WE[1*512 + rr]
                        + r2 * WE[2*512 + rr] + r3 * WE[3*512 + rr];
                wef[wp * 512 + rr] = a;
            }
        }
    }
    __syncthreads();

    // ============ Main body ==============================================
    const float* basep = fused + (size_t)(b * C_ + g * 8) * HWLR_;

    float fea[2][8];

    if (sh_fast) {
        // ---- shared 2-row x 3-col window serving both parities ----------
        const int y0 = byy + sh_dy;
        const int xg = m + sh_dxmin;
        const bool yv0 = (y0 >= 0) && (y0 < HLR_);
        const bool yv1 = (y0 + 1 >= 0) && (y0 + 1 < HLR_);
        const int yc0 = min(max(y0, 0), HLR_ - 1);
        const int yc1 = min(max(y0 + 1, 0), HLR_ - 1);
        const float wx0 = sh_wx[0], wx1 = sh_wx[1];
        const float wy0 = sh_wy[0], wy1 = sh_wy[1];
        const int o0 = sh_o0, o1 = sh_o1;

        bool xv[3]; int xc[3];
        #pragma unroll
        for (int k = 0; k < 3; k++) {
            int x = xg + k;
            xv[k] = (x >= 0) && (x < WLR_);
            xc[k] = min(max(x, 0), WLR_ - 1);
        }

        #pragma unroll
        for (int i = 0; i < 8; i++) {
            const float* pl = basep + (size_t)i * HWLR_;
            const float* r0 = pl + yc0 * WLR_;
            const float* r1 = pl + yc1 * WLR_;
            float u[3], vv[3];
            #pragma unroll
            for (int k = 0; k < 3; k++) {
                u[k]  = (yv0 && xv[k]) ? r0[xc[k]] : 0.0f;
                vv[k] = (yv1 && xv[k]) ? r1[xc[k]] : 0.0f;
            }
            {
                float ua = o0 ? u[1] : u[0],  ub = o0 ? u[2] : u[1];
                float va = o0 ? vv[1] : vv[0], vb = o0 ? vv[2] : vv[1];
                float top = ua * (1.0f - wx0) + ub * wx0;
                float bot = va * (1.0f - wx0) + vb * wx0;
                fea[0][i] = top * (1.0f - wy0) + bot * wy0;
            }
            {
                float ua = o1 ? u[1] : u[0],  ub = o1 ? u[2] : u[1];
                float va = o1 ? vv[1] : vv[0], vb = o1 ? vv[2] : vv[1];
                float top = ua * (1.0f - wx1) + ub * wx1;
                float bot = va * (1.0f - wx1) + vb * wx1;
                fea[1][i] = top * (1.0f - wy1) + bot * wy1;
            }
        }
    } else {
        // ---- generic fallback: independent 4-tap gather per parity -------
        #pragma unroll
        for (int q = 0; q < 2; q++) {
            float px = (float)m + (q + 0.5f) * 0.5f - 0.5f + sh_offx[q];
            float py = (float)byy + (hp + 0.5f) * 0.5f - 0.5f + sh_offy[q];
            float x0f = floorf(px), y0f = floorf(py);
            float wx = px - x0f, wy = py - y0f;
            int x0 = (int)x0f, y0 = (int)y0f;
            bool vx0 = (x0 >= 0) && (x0 < WLR_);
            bool vx1 = (x0 + 1 >= 0) && (x0 + 1 < WLR_);
            bool vy0 = (y0 >= 0) && (y0 < HLR_);
            bool vy1 = (y0 + 1 >= 0) && (y0 + 1 < HLR_);
            float w00 = (vy0 && vx0) ? (1.0f - wx) * (1.0f - wy) : 0.0f;
            float w01 = (vy0 && vx1) ? wx * (1.0f - wy)          : 0.0f;
            float w10 = (vy1 && vx0) ? (1.0f - wx) * wy          : 0.0f;
            float w11 = (vy1 && vx1) ? wx * wy                   : 0.0f;
            int xc0 = min(max(x0, 0), WLR_ - 1);
            int xc1 = min(max(x0 + 1, 0), WLR_ - 1);
            int yc0 = min(max(y0, 0), HLR_ - 1);
            int yc1 = min(max(y0 + 1, 0), HLR_ - 1);
            #pragma unroll
            for (int i = 0; i < 8; i++) {
                const float* pl = basep + (size_t)i * HWLR_;
                const float* r0 = pl + yc0 * WLR_;
                const float* r1 = pl + yc1 * WLR_;
                fea[q][i] = r0[xc0] * w00 + r0[xc1] * w01
                          + r1[xc0] * w10 + r1[xc1] * w11;
            }
        }
    }

    // ---- Compress (8x8 matvec) for both parities ------------------------
    #pragma unroll
    for (int q = 0; q < 2; q++) {
        const float4* wc4 = (const float4*)&s_wc[q][0][g * 8];  // row stride 16 f4
        float4 fa = make_float4(fea[q][0], fea[q][1], fea[q][2], fea[q][3]);
        float4 fb = make_float4(fea[q][4], fea[q][5], fea[q][6], fea[q][7]);
        #pragma unroll
        for (int j = 0; j < 8; j++) {
            float4 wa = wc4[j * 16];
            float4 wb = wc4[j * 16 + 1];
            float a = wa.x * fa.x + wa.y * fa.y + wa.z * fa.z + wa.w * fa.w
                    + wb.x * fb.x + wb.y * fb.y + wb.z * fb.z + wb.w * fb.w;
            s_part[j][g][q][ml] = a;
        }
    }
    __syncthreads();

    // ---- Reduce partials over channel groups: 16 warps <-> (j,q) --------
    {
        const int j = ww >> 1, qq = ww & 1;
        float s0 = 0.0f, s1 = 0.0f;
        #pragma unroll
        for (int gg = 0; gg < 8; gg++) {
            s0 += s_part[j][gg][qq][l];
            s1 += s_part[j][gg][qq][l + 32];
        }
        s_midf[j][qq][l]      = s0;
        s_midf[j][qq][l + 32] = s1;
    }
    __syncthreads();

    // ---- Expand + residual + contiguous float2 stores -------------------
    float mid0[8], mid1[8];
    #pragma unroll
    for (int j = 0; j < 8; j++) {
        mid0[j] = s_midf[j][0][ml];
        mid1[j] = s_midf[j][1][ml];
    }
    float* obp = out + ((size_t)(b * C_ + g * 8) * HHR_ + h) * WHR_ + 2 * m;
    #pragma unroll
    for (int i = 0; i < 8; i++) {
        const float4* we0 = (const float4*)&s_we[0][g * 8 + i][0];
        const float4* we1 = (const float4*)&s_we[1][g * 8 + i][0];
        float4 ea0 = we0[0], eb0 = we0[1];
        float4 ea1 = we1[0], eb1 = we1[1];
        float r0 = fea[0][i]
                 + ea0.x * mid0[0] + ea0.y * mid0[1] + ea0.z * mid0[2] + ea0.w * mid0[3]
                 + eb0.x * mid0[4] + eb0.y * mid0[5] + eb0.z * mid0[6] + eb0.w * mid0[7];
        float r1 = fea[1][i]
                 + ea1.x * mid1[0] + ea1.y * mid1[1] + ea1.z * mid1[2] + ea1.w * mid1[3]
                 + eb1.x * mid1[4] + eb1.y * mid1[5] + eb1.z * mid1[6] + eb1.w * mid1[7];
        float2 rv = make_float2(r0, r1);
        *(float2*)(obp + (size_t)i * HWHR_) = rv;
    }
}

// ---------------------------------------------------------------------------
extern "C" void kernel_launch(void* const* d_in, const int* in_sizes, int n_in,
                              void* d_out, int out_size)
{
    const float* fused = (const float*)d_in[1];
    const float* WC    = (const float*)d_in[2];
    const float* WE    = (const float*)d_in[3];
    const float* w1    = (const float*)d_in[4];
    const float* b1    = (const float*)d_in[5];
    const float* w2    = (const float*)d_in[6];
    const float* b2    = (const float*)d_in[7];
    const float* rw    = (const float*)d_in[8];
    const float* rb    = (const float*)d_in[9];
    const float* ow    = (const float*)d_in[10];
    const float* obv   = (const float*)d_in[11];
    float* out = (float*)d_out;

    dim3 grid(WHR_ / 128, HHR_, B_);
    upsample_fused<<<grid, 512>>>(fused, out,
                                  w1, b1, w2, b2, rw, rb, ow, obv, WC, WE);
}

// round 7
// speedup vs baseline: 2.3006x; 2.3006x over previous
#include <cuda_runtime.h>
#include <cuda_bf16.h>
#include <math.h>

// Problem constants (fixed by the dataset)
#define B_   2
#define C_   64
#define E_   4
#define HLR_ 192
#define WLR_ 192
#define HHR_ 384
#define WHR_ 384
#define HWLR_ (HLR_*WLR_)
#define HWHR_ (HHR_*WHR_)

// Precomputed per-parity quantities (4 variants: hp*2+wp)
__device__ float g_wc[2][2][8][64];    // dynamic compress weights [hp][wp][j][c]
__device__ float g_we[2][2][64][8];    // dynamic expand weights   [hp][wp][c][j]
__device__ float g_offx[2][2], g_offy[2][2];   // raw offsets (fallback path)
__device__ int   g_fast[2];            // per-hp: fast window path valid
__device__ int   g_dyf[2];             // fast: shared y0 delta (rel. to byy)
__device__ int   g_dxmin[2];           // fast: window base delta (rel. to m)
__device__ int   g_ox[2][2];           // fast: per-q tap offset in window (0/1)
__device__ float g_wxf[2][2], g_wyf[2][2];     // fast: per-q fracs

// ---------------------------------------------------------------------------
// Kernel 0 (fast): 1 block x 1024 threads.
//   A: e1 table (256 threads, float4 w1)
//   B: emb = relu(w2 @ e1 + b2): 4 lanes per output, float4 + shfl reduce
//   C: routing / offsets: same split-dot pattern
//   D: derived window constants + float4 routing-mix of WC/WE into g_wc/g_we
// ---------------------------------------------------------------------------
__global__ void __launch_bounds__(1024) precompute_kernel(
    const float* __restrict__ w1, const float* __restrict__ b1,
    const float* __restrict__ w2, const float* __restrict__ b2,
    const float* __restrict__ rw, const float* __restrict__ rb,
    const float* __restrict__ ow, const float* __restrict__ ob,
    const float* __restrict__ WC, const float* __restrict__ WE)
{
    __shared__ float s_e1[4][64];
    __shared__ float s_emb[4][64];
    __shared__ float s_rt[4][4];
    __shared__ float s_off[4][2];

    const int tid = threadIdx.x;

    // ---- A: first-layer activations, one thread per (variant, k) ---------
    if (tid < 256) {
        int v = tid >> 6, k = tid & 63;
        int hp = v >> 1, wp = v & 1;
        float ch = (hp + 0.5f) * 0.5f; ch = ch - floorf(ch + 0.001f) - 0.5f;
        float cw = (wp + 0.5f) * 0.5f; cw = cw - floorf(cw + 0.001f) - 0.5f;
        float4 wv = ((const float4*)w1)[k];
        float e1 = b1[k] + wv.x * 0.5f + wv.y * 0.5f + wv.z * ch + wv.w * cw;
        s_e1[v][k] = fmaxf(e1, 0.0f);
    }
    __syncthreads();

    // ---- B: second layer, 4 lanes per output -----------------------------
    {
        int v = tid >> 8, o = (tid >> 2) & 63, part = tid & 3;
        const float4* w2v = (const float4*)(w2 + o * 64 + part * 16);
        const float*  e1p = &s_e1[v][part * 16];
        float acc = 0.0f;
        #pragma unroll
        for (int t = 0; t < 4; t++) {
            float4 wv = w2v[t];
            acc += wv.x * e1p[t*4+0] + wv.y * e1p[t*4+1]
                 + wv.z * e1p[t*4+2] + wv.w * e1p[t*4+3];
        }
        acc += __shfl_xor_sync(0xFFFFFFFFu, acc, 1);
        acc += __shfl_xor_sync(0xFFFFFFFFu, acc, 2);
        if (part == 0) s_emb[v][o] = fmaxf(acc + b2[o], 0.0f);
    }
    __syncthreads();

    // ---- C: routing (tid<64) and offsets (tid in [64,96)) ----------------
    if (tid < 64) {
        int v = tid >> 4, e = (tid >> 2) & 3, part = tid & 3;
        const float4* rwv = (const float4*)(rw + e * 64 + part * 16);
        const float*  emp = &s_emb[v][part * 16];
        float acc = 0.0f;
        #pragma unroll
        for (int t = 0; t < 4; t++) {
            float4 wv = rwv[t];
            acc += wv.x * emp[t*4+0] + wv.y * emp[t*4+1]
                 + wv.z * emp[t*4+2] + wv.w * emp[t*4+3];
        }
        acc += __shfl_xor_sync(0xFFFFFFFFu, acc, 1);
        acc += __shfl_xor_sync(0xFFFFFFFFu, acc, 2);
        if (part == 0) s_rt[v][e] = 1.0f / (1.0f + expf(-(acc + rb[e])));
    } else if (tid < 96) {
        int idx = tid - 64;               // lane = idx (warp 2)
        int v = idx >> 3, k = (idx >> 2) & 1, part = idx & 3;
        const float4* owv = (const float4*)(ow + k * 64 + part * 16);
        const float*  emp = &s_emb[v][part * 16];
        float acc = 0.0f;
        #pragma unroll
        for (int t = 0; t < 4; t++) {
            float4 wv = owv[t];
            acc += wv.x * emp[t*4+0] + wv.y * emp[t*4+1]
                 + wv.z * emp[t*4+2] + wv.w * emp[t*4+3];
        }
        acc += __shfl_xor_sync(0xFFFFFFFFu, acc, 1);
        acc += __shfl_xor_sync(0xFFFFFFFFu, acc, 2);
        if (part == 0) s_off[v][k] = acc + ob[k];
    }
    __syncthreads();

    // ---- derived window constants (one thread per hp) --------------------
    if (tid < 2) {
        int hpp = tid;
        float ox0 = s_off[hpp*2 + 0][0], oy0 = s_off[hpp*2 + 0][1];
        float ox1 = s_off[hpp*2 + 1][0], oy1 = s_off[hpp*2 + 1][1];
        g_offx[hpp][0] = ox0; g_offx[hpp][1] = ox1;
        g_offy[hpp][0] = oy0; g_offy[hpp][1] = oy1;
        float tx0 = -0.25f + ox0;
        float tx1 =  0.25f + ox1;
        float tyb = (hpp + 0.5f) * 0.5f - 0.5f;
        float ty0 = tyb + oy0;
        float ty1 = tyb + oy1;
        float fx0 = floorf(tx0), fx1 = floorf(tx1);
        float fy0 = floorf(ty0), fy1 = floorf(ty1);
        int dx0 = (int)fx0, dx1 = (int)fx1;
        int dy0 = (int)fy0, dy1 = (int)fy1;
        g_fast[hpp] = (dy0 == dy1) && (abs(dx1 - dx0) <= 1);
        int dmn = min(dx0, dx1);
        g_dyf[hpp]   = dy0;
        g_dxmin[hpp] = dmn;
        g_ox[hpp][0] = dx0 - dmn;
        g_ox[hpp][1] = dx1 - dmn;
        g_wxf[hpp][0] = tx0 - fx0;  g_wxf[hpp][1] = tx1 - fx1;
        g_wyf[hpp][0] = ty0 - fy0;  g_wyf[hpp][1] = ty1 - fy1;
    }
    __syncthreads();

    // ---- D: routing-mix dynamic weights, float4 lanes ---------------------
    {
        if (tid < 512) {                 // wc: v = tid>>7, r4 = tid&127
            int v = tid >> 7, r4 = tid & 127;
            float r0 = s_rt[v][0], r1 = s_rt[v][1], r2 = s_rt[v][2], r3 = s_rt[v][3];
            const float4* wc4 = (const float4*)WC;
            float4 a0 = wc4[0*128 + r4], a1 = wc4[1*128 + r4];
            float4 a2 = wc4[2*128 + r4], a3 = wc4[3*128 + r4];
            float4 o4;
            o4.x = r0*a0.x + r1*a1.x + r2*a2.x + r3*a3.x;
            o4.y = r0*a0.y + r1*a1.y + r2*a2.y + r3*a3.y;
            o4.z = r0*a0.z + r1*a1.z + r2*a2.z + r3*a3.z;
            o4.w = r0*a0.w + r1*a1.w + r2*a2.w + r3*a3.w;
            ((float4*)&g_wc[0][0][0][0])[v * 128 + r4] = o4;
        } else {                          // we
            int t = tid - 512;
            int v = t >> 7, r4 = t & 127;
            float r0 = s_rt[v][0], r1 = s_rt[v][1], r2 = s_rt[v][2], r3 = s_rt[v][3];
            const float4* we4 = (const float4*)WE;
            float4 a0 = we4[0*128 + r4], a1 = we4[1*128 + r4];
            float4 a2 = we4[2*128 + r4], a3 = we4[3*128 + r4];
            float4 o4;
            o4.x = r0*a0.x + r1*a1.x + r2*a2.x + r3*a3.x;
            o4.y = r0*a0.y + r1*a1.y + r2*a2.y + r3*a3.y;
            o4.z = r0*a0.z + r1*a1.z + r2*a2.z + r3*a3.z;
            o4.w = r0*a0.w + r1*a1.w + r2*a2.w + r3*a3.w;
            ((float4*)&g_we[0][0][0][0])[v * 128 + r4] = o4;
        }
    }
}

// ---------------------------------------------------------------------------
// Main kernel. Block = 512 threads = 16 warps, 3 blocks/SM.
//   warp ww: g = ww & 7 (channel group of 8), half = ww >> 3.
//   lane l -> LR column m = mbase + half*32 + l; thread produces BOTH
//   w-parities (shared bilinear window, float2 stores). Register pressure is
//   kept <=42 by parking fea0 / q0-results in a same-thread smem buffer.
// grid = (WHR/128, HHR, B).
// ---------------------------------------------------------------------------
__global__ void __launch_bounds__(512, 3) upsample_main(
    const float* __restrict__ fused, float* __restrict__ out)
{
    __shared__ float s_wc[2][8][64];        // [q][j][c]
    __shared__ float s_we[2][64][8];        // [q][c][j]
    __shared__ float s_part[8][8][2][64];   // [j][g][q][m]
    __shared__ float s_midf[8][2][64];      // [j][q][m]
    __shared__ float s_buf[8][8][64];       // [g][i][m]  fea0, then q0 results

    const int tid  = threadIdx.x;
    const int l    = tid & 31;
    const int ww   = tid >> 5;
    const int g    = ww & 7;
    const int half = ww >> 3;
    const int h    = blockIdx.y;
    const int hp   = h & 1;
    const int byy  = h >> 1;
    const int b    = blockIdx.z;
    const int mbase = blockIdx.x * 64;
    const int ml   = half * 32 + l;          // m within tile [0,64)
    const int m    = mbase + ml;             // LR column

    // Stage dynamic weights: 512 float4 (wc 256 + we 256), one per thread.
    {
        const float4* srcc = (const float4*)&g_wc[hp][0][0][0];
        const float4* srce = (const float4*)&g_we[hp][0][0][0];
        float4* dc = (float4*)&s_wc[0][0][0];
        float4* de = (float4*)&s_we[0][0][0];
        if (tid < 256) dc[tid] = srcc[tid];
        else           de[tid - 256] = srce[tid - 256];
    }
    __syncthreads();

    const float* basep = fused + (size_t)(b * C_ + g * 8) * HWLR_;

    float fea0[8], fea1[8];

    if (g_fast[hp]) {
        // ---- shared 2-row x 3-col window serving both parities ----------
        const int y0 = byy + g_dyf[hp];
        const int xg = m + g_dxmin[hp];
        const bool yv0 = (y0 >= 0) && (y0 < HLR_);
        const bool yv1 = (y0 + 1 >= 0) && (y0 + 1 < HLR_);
        const int yc0 = min(max(y0, 0), HLR_ - 1);
        const int yc1 = min(max(y0 + 1, 0), HLR_ - 1);
        const float wx0 = g_wxf[hp][0], wx1 = g_wxf[hp][1];
        const float wy0 = g_wyf[hp][0], wy1 = g_wyf[hp][1];
        const int o0 = g_ox[hp][0], o1 = g_ox[hp][1];

        bool xv[3]; int xc[3];
        #pragma unroll
        for (int k = 0; k < 3; k++) {
            int x = xg + k;
            xv[k] = (x >= 0) && (x < WLR_);
            xc[k] = min(max(x, 0), WLR_ - 1);
        }

        #pragma unroll
        for (int i = 0; i < 8; i++) {
            const float* pl = basep + (size_t)i * HWLR_;
            const float* r0 = pl + yc0 * WLR_;
            const float* r1 = pl + yc1 * WLR_;
            float u[3], vv[3];
            #pragma unroll
            for (int k = 0; k < 3; k++) {
                u[k]  = (yv0 && xv[k]) ? r0[xc[k]] : 0.0f;
                vv[k] = (yv1 && xv[k]) ? r1[xc[k]] : 0.0f;
            }
            {
                float ua = o0 ? u[1] : u[0],  ub = o0 ? u[2] : u[1];
                float va = o0 ? vv[1] : vv[0], vb = o0 ? vv[2] : vv[1];
                float top = ua * (1.0f - wx0) + ub * wx0;
                float bot = va * (1.0f - wx0) + vb * wx0;
                fea0[i] = top * (1.0f - wy0) + bot * wy0;
            }
            {
                float ua = o1 ? u[1] : u[0],  ub = o1 ? u[2] : u[1];
                float va = o1 ? vv[1] : vv[0], vb = o1 ? vv[2] : vv[1];
                float top = ua * (1.0f - wx1) + ub * wx1;
                float bot = va * (1.0f - wx1) + vb * wx1;
                fea1[i] = top * (1.0f - wy1) + bot * wy1;
            }
        }
    } else {
        // ---- generic fallback: independent 4-tap gather per parity -------
        #pragma unroll
        for (int q = 0; q < 2; q++) {
            float px = (float)m + (q + 0.5f) * 0.5f - 0.5f + g_offx[hp][q];
            float py = (float)byy + (hp + 0.5f) * 0.5f - 0.5f + g_offy[hp][q];
            float x0f = floorf(px), y0f = floorf(py);
            float wx = px - x0f, wy = py - y0f;
            int x0 = (int)x0f, y0 = (int)y0f;
            bool vx0 = (x0 >= 0) && (x0 < WLR_);
            bool vx1 = (x0 + 1 >= 0) && (x0 + 1 < WLR_);
            bool vy0 = (y0 >= 0) && (y0 < HLR_);
            bool vy1 = (y0 + 1 >= 0) && (y0 + 1 < HLR_);
            float w00 = (vy0 && vx0) ? (1.0f - wx) * (1.0f - wy) : 0.0f;
            float w01 = (vy0 && vx1) ? wx * (1.0f - wy)          : 0.0f;
            float w10 = (vy1 && vx0) ? (1.0f - wx) * wy          : 0.0f;
            float w11 = (vy1 && vx1) ? wx * wy                   : 0.0f;
            int xc0 = min(max(x0, 0), WLR_ - 1);
            int xc1 = min(max(x0 + 1, 0), WLR_ - 1);
            int yc0 = min(max(y0, 0), HLR_ - 1);
            int yc1 = min(max(y0 + 1, 0), HLR_ - 1);
            float* dst = q ? fea1 : fea0;
            #pragma unroll
            for (int i = 0; i < 8; i++) {
                const float* pl = basep + (size_t)i * HWLR_;
                const float* r0 = pl + yc0 * WLR_;
                const float* r1 = pl + yc1 * WLR_;
                dst[i] = r0[xc0] * w00 + r0[xc1] * w01
                       + r1[xc0] * w10 + r1[xc1] * w11;
            }
        }
    }

    // ---- Compress q=0, then park fea0 in smem, then compress q=1 --------
    {
        const float4* wc4 = (const float4*)&s_wc[0][0][g * 8];
        float4 fa = make_float4(fea0[0], fea0[1], fea0[2], fea0[3]);
        float4 fb = make_float4(fea0[4], fea0[5], fea0[6], fea0[7]);
        #pragma unroll
        for (int j = 0; j < 8; j++) {
            float4 wa = wc4[j * 16];
            float4 wb = wc4[j * 16 + 1];
            float a = wa.x * fa.x + wa.y * fa.y + wa.z * fa.z + wa.w * fa.w
                    + wb.x * fb.x + wb.y * fb.y + wb.z * fb.z + wb.w * fb.w;
            s_part[j][g][0][ml] = a;
        }
    }
    #pragma unroll
    for (int i = 0; i < 8; i++) s_buf[g][i][ml] = fea0[i];   // fea0 regs die here
    {
        const float4* wc4 = (const float4*)&s_wc[1][0][g * 8];
        float4 fa = make_float4(fea1[0], fea1[1], fea1[2], fea1[3]);
        float4 fb = make_float4(fea1[4], fea1[5], fea1[6], fea1[7]);
        #pragma unroll
        for (int j = 0; j < 8; j++) {
            float4 wa = wc4[j * 16];
            float4 wb = wc4[j * 16 + 1];
            float a = wa.x * fa.x + wa.y * fa.y + wa.z * fa.z + wa.w * fa.w
                    + wb.x * fb.x + wb.y * fb.y + wb.z * fb.z + wb.w * fb.w;
            s_part[j][g][1][ml] = a;
        }
    }
    __syncthreads();

    // ---- Reduce partials over channel groups: 16 warps <-> (j,q) --------
    {
        const int j = ww >> 1, qq = ww & 1;
        float s0 = 0.0f, s1 = 0.0f;
        #pragma unroll
        for (int gg = 0; gg < 8; gg++) {
            s0 += s_part[j][gg][qq][l];
            s1 += s_part[j][gg][qq][l + 32];
        }
        s_midf[j][qq][l]      = s0;
        s_midf[j][qq][l + 32] = s1;
    }
    __syncthreads();

    // ---- Expand q=0: results back into s_buf (same-thread, no sync) -----
    {
        float mid[8];
        #pragma unroll
        for (int j = 0; j < 8; j++) mid[j] = s_midf[j][0][ml];
        #pragma unroll
        for (int i = 0; i < 8; i++) {
            const float4* we0 = (const float4*)&s_we[0][g * 8 + i][0];
            float4 ea = we0[0], eb = we0[1];
            float r0 = s_buf[g][i][ml]
                     + ea.x * mid[0] + ea.y * mid[1] + ea.z * mid[2] + ea.w * mid[3]
                     + eb.x * mid[4] + eb.y * mid[5] + eb.z * mid[6] + eb.w * mid[7];
            s_buf[g][i][ml] = r0;
        }
    }
    // ---- Expand q=1 + paired float2 stores -------------------------------
    {
        float mid[8];
        #pragma unroll
        for (int j = 0; j < 8; j++) mid[j] = s_midf[j][1][ml];
        float* obp = out + ((size_t)(b * C_ + g * 8) * HHR_ + h) * WHR_ + 2 * m;
        #pragma unroll
        for (int i = 0; i < 8; i++) {
            const float4* we1 = (const float4*)&s_we[1][g * 8 + i][0];
            float4 ea = we1[0], eb = we1[1];
            float r1 = fea1[i]
                     + ea.x * mid[0] + ea.y * mid[1] + ea.z * mid[2] + ea.w * mid[3]
                     + eb.x * mid[4] + eb.y * mid[5] + eb.z * mid[6] + eb.w * mid[7];
            float2 rv = make_float2(s_buf[g][i][ml], r1);
            *(float2*)(obp + (size_t)i * HWHR_) = rv;
        }
    }
}

// ---------------------------------------------------------------------------
extern "C" void kernel_launch(void* const* d_in, const int* in_sizes, int n_in,
                              void* d_out, int out_size)
{
    const float* fused = (const float*)d_in[1];
    const float* WC    = (const float*)d_in[2];
    const float* WE    = (const float*)d_in[3];
    const float* w1    = (const float*)d_in[4];
    const float* b1    = (const float*)d_in[5];
    const float* w2    = (const float*)d_in[6];
    const float* b2    = (const float*)d_in[7];
    const float* rw    = (const float*)d_in[8];
    const float* rb    = (const float*)d_in[9];
    const float* ow    = (const float*)d_in[10];
    const float* obv   = (const float*)d_in[11];
    float* out = (float*)d_out;

    precompute_kernel<<<1, 1024>>>(w1, b1, w2, b2, rw, rb, ow, obv, WC, WE);

    dim3 grid(WHR_ / 128, HHR_, B_);
    upsample_main<<<grid, 512>>>(fused, out);
}

// round 8
// speedup vs baseline: 2.7045x; 1.1756x over previous
#include <cuda_runtime.h>
#include <cuda_bf16.h>
#include <math.h>

// Problem constants (fixed by the dataset)
#define B_   2
#define C_   64
#define E_   4
#define HLR_ 192
#define WLR_ 192
#define HHR_ 384
#define WHR_ 384
#define HWLR_ (HLR_*WLR_)
#define HWHR_ (HHR_*WHR_)

// Precomputed per-parity quantities (4 variants: hp*2+wp)
__device__ float g_wc[2][2][8][64];    // dynamic compress weights [hp][wp][j][c]
__device__ float g_we[2][2][64][8];    // dynamic expand weights   [hp][wp][c][j]
__device__ float g_offx[2][2], g_offy[2][2];   // raw offsets (fallback path)
__device__ int   g_fast[2];            // per-hp: fast window path valid
__device__ int   g_dyf[2];             // fast: shared y0 delta (rel. to byy)
__device__ int   g_dxmin[2];           // fast: window base delta (rel. to m)
__device__ int   g_ox[2][2];           // fast: per-q tap offset in window (0/1)
__device__ float g_wxf[2][2], g_wyf[2][2];     // fast: per-q fracs

// ---------------------------------------------------------------------------
// Kernel 0 (fast, from R7): 1 block x 1024 threads.
// ---------------------------------------------------------------------------
__global__ void __launch_bounds__(1024) precompute_kernel(
    const float* __restrict__ w1, const float* __restrict__ b1,
    const float* __restrict__ w2, const float* __restrict__ b2,
    const float* __restrict__ rw, const float* __restrict__ rb,
    const float* __restrict__ ow, const float* __restrict__ ob,
    const float* __restrict__ WC, const float* __restrict__ WE)
{
    __shared__ float s_e1[4][64];
    __shared__ float s_emb[4][64];
    __shared__ float s_rt[4][4];
    __shared__ float s_off[4][2];

    const int tid = threadIdx.x;

    // ---- A: first-layer activations, one thread per (variant, k) ---------
    if (tid < 256) {
        int v = tid >> 6, k = tid & 63;
        int hp = v >> 1, wp = v & 1;
        float ch = (hp + 0.5f) * 0.5f; ch = ch - floorf(ch + 0.001f) - 0.5f;
        float cw = (wp + 0.5f) * 0.5f; cw = cw - floorf(cw + 0.001f) - 0.5f;
        float4 wv = ((const float4*)w1)[k];
        float e1 = b1[k] + wv.x * 0.5f + wv.y * 0.5f + wv.z * ch + wv.w * cw;
        s_e1[v][k] = fmaxf(e1, 0.0f);
    }
    __syncthreads();

    // ---- B: second layer, 4 lanes per output -----------------------------
    {
        int v = tid >> 8, o = (tid >> 2) & 63, part = tid & 3;
        const float4* w2v = (const float4*)(w2 + o * 64 + part * 16);
        const float*  e1p = &s_e1[v][part * 16];
        float acc = 0.0f;
        #pragma unroll
        for (int t = 0; t < 4; t++) {
            float4 wv = w2v[t];
            acc += wv.x * e1p[t*4+0] + wv.y * e1p[t*4+1]
                 + wv.z * e1p[t*4+2] + wv.w * e1p[t*4+3];
        }
        acc += __shfl_xor_sync(0xFFFFFFFFu, acc, 1);
        acc += __shfl_xor_sync(0xFFFFFFFFu, acc, 2);
        if (part == 0) s_emb[v][o] = fmaxf(acc + b2[o], 0.0f);
    }
    __syncthreads();

    // ---- C: routing (tid<64) and offsets (tid in [64,96)) ----------------
    if (tid < 64) {
        int v = tid >> 4, e = (tid >> 2) & 3, part = tid & 3;
        const float4* rwv = (const float4*)(rw + e * 64 + part * 16);
        const float*  emp = &s_emb[v][part * 16];
        float acc = 0.0f;
        #pragma unroll
        for (int t = 0; t < 4; t++) {
            float4 wv = rwv[t];
            acc += wv.x * emp[t*4+0] + wv.y * emp[t*4+1]
                 + wv.z * emp[t*4+2] + wv.w * emp[t*4+3];
        }
        acc += __shfl_xor_sync(0xFFFFFFFFu, acc, 1);
        acc += __shfl_xor_sync(0xFFFFFFFFu, acc, 2);
        if (part == 0) s_rt[v][e] = 1.0f / (1.0f + expf(-(acc + rb[e])));
    } else if (tid < 96) {
        int idx = tid - 64;
        int v = idx >> 3, k = (idx >> 2) & 1, part = idx & 3;
        const float4* owv = (const float4*)(ow + k * 64 + part * 16);
        const float*  emp = &s_emb[v][part * 16];
        float acc = 0.0f;
        #pragma unroll
        for (int t = 0; t < 4; t++) {
            float4 wv = owv[t];
            acc += wv.x * emp[t*4+0] + wv.y * emp[t*4+1]
                 + wv.z * emp[t*4+2] + wv.w * emp[t*4+3];
        }
        acc += __shfl_xor_sync(0xFFFFFFFFu, acc, 1);
        acc += __shfl_xor_sync(0xFFFFFFFFu, acc, 2);
        if (part == 0) s_off[v][k] = acc + ob[k];
    }
    __syncthreads();

    // ---- derived window constants (one thread per hp) --------------------
    if (tid < 2) {
        int hpp = tid;
        float ox0 = s_off[hpp*2 + 0][0], oy0 = s_off[hpp*2 + 0][1];
        float ox1 = s_off[hpp*2 + 1][0], oy1 = s_off[hpp*2 + 1][1];
        g_offx[hpp][0] = ox0; g_offx[hpp][1] = ox1;
        g_offy[hpp][0] = oy0; g_offy[hpp][1] = oy1;
        float tx0 = -0.25f + ox0;
        float tx1 =  0.25f + ox1;
        float tyb = (hpp + 0.5f) * 0.5f - 0.5f;
        float ty0 = tyb + oy0;
        float ty1 = tyb + oy1;
        float fx0 = floorf(tx0), fx1 = floorf(tx1);
        float fy0 = floorf(ty0), fy1 = floorf(ty1);
        int dx0 = (int)fx0, dx1 = (int)fx1;
        int dy0 = (int)fy0, dy1 = (int)fy1;
        g_fast[hpp] = (dy0 == dy1) && (abs(dx1 - dx0) <= 1);
        int dmn = min(dx0, dx1);
        g_dyf[hpp]   = dy0;
        g_dxmin[hpp] = dmn;
        g_ox[hpp][0] = dx0 - dmn;
        g_ox[hpp][1] = dx1 - dmn;
        g_wxf[hpp][0] = tx0 - fx0;  g_wxf[hpp][1] = tx1 - fx1;
        g_wyf[hpp][0] = ty0 - fy0;  g_wyf[hpp][1] = ty1 - fy1;
    }
    __syncthreads();

    // ---- D: routing-mix dynamic weights, float4 lanes ---------------------
    {
        if (tid < 512) {
            int v = tid >> 7, r4 = tid & 127;
            float r0 = s_rt[v][0], r1 = s_rt[v][1], r2 = s_rt[v][2], r3 = s_rt[v][3];
            const float4* wc4 = (const float4*)WC;
            float4 a0 = wc4[0*128 + r4], a1 = wc4[1*128 + r4];
            float4 a2 = wc4[2*128 + r4], a3 = wc4[3*128 + r4];
            float4 o4;
            o4.x = r0*a0.x + r1*a1.x + r2*a2.x + r3*a3.x;
            o4.y = r0*a0.y + r1*a1.y + r2*a2.y + r3*a3.y;
            o4.z = r0*a0.z + r1*a1.z + r2*a2.z + r3*a3.z;
            o4.w = r0*a0.w + r1*a1.w + r2*a2.w + r3*a3.w;
            ((float4*)&g_wc[0][0][0][0])[v * 128 + r4] = o4;
        } else {
            int t = tid - 512;
            int v = t >> 7, r4 = t & 127;
            float r0 = s_rt[v][0], r1 = s_rt[v][1], r2 = s_rt[v][2], r3 = s_rt[v][3];
            const float4* we4 = (const float4*)WE;
            float4 a0 = we4[0*128 + r4], a1 = we4[1*128 + r4];
            float4 a2 = we4[2*128 + r4], a3 = we4[3*128 + r4];
            float4 o4;
            o4.x = r0*a0.x + r1*a1.x + r2*a2.x + r3*a3.x;
            o4.y = r0*a0.y + r1*a1.y + r2*a2.y + r3*a3.y;
            o4.z = r0*a0.z + r1*a1.z + r2*a2.z + r3*a3.z;
            o4.w = r0*a0.w + r1*a1.w + r2*a2.w + r3*a3.w;
            ((float4*)&g_we[0][0][0][0])[v * 128 + r4] = o4;
        }
    }
}

// ---------------------------------------------------------------------------
// Main kernel (R5 body, fastest measured). Block = 512 threads = 16 warps.
//   warp ww: g = ww & 7 (channel group of 8), half = ww >> 3.
//   lane l -> LR column m = mbase + half*32 + l; thread produces BOTH
//   w-parities (HR cols w=2m, 2m+1): shared bilinear window, shared weights,
//   contiguous float2 stores.
// grid = (WHR/128, HHR, B).
// ---------------------------------------------------------------------------
__global__ void __launch_bounds__(512) upsample_main(
    const float* __restrict__ fused, float* __restrict__ out)
{
    __shared__ float s_wc[2][8][64];        // [q][j][c]
    __shared__ float s_we[2][64][8];        // [q][c][j]
    __shared__ float s_part[8][8][2][64];   // [j][g][q][m]
    __shared__ float s_midf[8][2][64];      // [j][q][m]

    const int tid  = threadIdx.x;
    const int l    = tid & 31;
    const int ww   = tid >> 5;
    const int g    = ww & 7;
    const int half = ww >> 3;
    const int h    = blockIdx.y;
    const int hp   = h & 1;
    const int byy  = h >> 1;
    const int b    = blockIdx.z;
    const int mbase = blockIdx.x * 64;
    const int ml   = half * 32 + l;          // m within tile [0,64)
    const int m    = mbase + ml;             // LR column

    // Stage dynamic weights: 512 float4 (wc 256 + we 256), one per thread.
    {
        const float4* srcc = (const float4*)&g_wc[hp][0][0][0];
        const float4* srce = (const float4*)&g_we[hp][0][0][0];
        float4* dc = (float4*)&s_wc[0][0][0];
        float4* de = (float4*)&s_we[0][0][0];
        if (tid < 256) dc[tid] = srcc[tid];
        else           de[tid - 256] = srce[tid - 256];
    }
    __syncthreads();

    const float* basep = fused + (size_t)(b * C_ + g * 8) * HWLR_;

    float fea[2][8];

    if (g_fast[hp]) {
        // ---- shared 2-row x 3-col window serving both parities ----------
        const int y0 = byy + g_dyf[hp];
        const int xg = m + g_dxmin[hp];
        const bool yv0 = (y0 >= 0) && (y0 < HLR_);
        const bool yv1 = (y0 + 1 >= 0) && (y0 + 1 < HLR_);
        const int yc0 = min(max(y0, 0), HLR_ - 1);
        const int yc1 = min(max(y0 + 1, 0), HLR_ - 1);
        const float wx0 = g_wxf[hp][0], wx1 = g_wxf[hp][1];
        const float wy0 = g_wyf[hp][0], wy1 = g_wyf[hp][1];
        const int o0 = g_ox[hp][0], o1 = g_ox[hp][1];

        bool xv[3]; int xc[3];
        #pragma unroll
        for (int k = 0; k < 3; k++) {
            int x = xg + k;
            xv[k] = (x >= 0) && (x < WLR_);
            xc[k] = min(max(x, 0), WLR_ - 1);
        }

        #pragma unroll
        for (int i = 0; i < 8; i++) {
            const float* pl = basep + (size_t)i * HWLR_;
            const float* r0 = pl + yc0 * WLR_;
            const float* r1 = pl + yc1 * WLR_;
            float u[3], vv[3];
            #pragma unroll
            for (int k = 0; k < 3; k++) {
                u[k]  = (yv0 && xv[k]) ? r0[xc[k]] : 0.0f;
                vv[k] = (yv1 && xv[k]) ? r1[xc[k]] : 0.0f;
            }
            {
                float ua = o0 ? u[1] : u[0],  ub = o0 ? u[2] : u[1];
                float va = o0 ? vv[1] : vv[0], vb = o0 ? vv[2] : vv[1];
                float top = ua * (1.0f - wx0) + ub * wx0;
                float bot = va * (1.0f - wx0) + vb * wx0;
                fea[0][i] = top * (1.0f - wy0) + bot * wy0;
            }
            {
                float ua = o1 ? u[1] : u[0],  ub = o1 ? u[2] : u[1];
                float va = o1 ? vv[1] : vv[0], vb = o1 ? vv[2] : vv[1];
                float top = ua * (1.0f - wx1) + ub * wx1;
                float bot = va * (1.0f - wx1) + vb * wx1;
                fea[1][i] = top * (1.0f - wy1) + bot * wy1;
            }
        }
    } else {
        // ---- generic fallback: independent 4-tap gather per parity -------
        #pragma unroll
        for (int q = 0; q < 2; q++) {
            float px = (float)m + (q + 0.5f) * 0.5f - 0.5f + g_offx[hp][q];
            float py = (float)byy + (hp + 0.5f) * 0.5f - 0.5f + g_offy[hp][q];
            float x0f = floorf(px), y0f = floorf(py);
            float wx = px - x0f, wy = py - y0f;
            int x0 = (int)x0f, y0 = (int)y0f;
            bool vx0 = (x0 >= 0) && (x0 < WLR_);
            bool vx1 = (x0 + 1 >= 0) && (x0 + 1 < WLR_);
            bool vy0 = (y0 >= 0) && (y0 < HLR_);
            bool vy1 = (y0 + 1 >= 0) && (y0 + 1 < HLR_);
            float w00 = (vy0 && vx0) ? (1.0f - wx) * (1.0f - wy) : 0.0f;
            float w01 = (vy0 && vx1) ? wx * (1.0f - wy)          : 0.0f;
            float w10 = (vy1 && vx0) ? (1.0f - wx) * wy          : 0.0f;
            float w11 = (vy1 && vx1) ? wx * wy                   : 0.0f;
            int xc0 = min(max(x0, 0), WLR_ - 1);
            int xc1 = min(max(x0 + 1, 0), WLR_ - 1);
            int yc0 = min(max(y0, 0), HLR_ - 1);
            int yc1 = min(max(y0 + 1, 0), HLR_ - 1);
            #pragma unroll
            for (int i = 0; i < 8; i++) {
                const float* pl = basep + (size_t)i * HWLR_;
                const float* r0 = pl + yc0 * WLR_;
                const float* r1 = pl + yc1 * WLR_;
                fea[q][i] = r0[xc0] * w00 + r0[xc1] * w01
                          + r1[xc0] * w10 + r1[xc1] * w11;
            }
        }
    }

    // ---- Compress (8x8 matvec) for both parities ------------------------
    #pragma unroll
    for (int q = 0; q < 2; q++) {
        const float4* wc4 = (const float4*)&s_wc[q][0][g * 8];  // row stride 16 f4
        float4 fa = make_float4(fea[q][0], fea[q][1], fea[q][2], fea[q][3]);
        float4 fb = make_float4(fea[q][4], fea[q][5], fea[q][6], fea[q][7]);
        #pragma unroll
        for (int j = 0; j < 8; j++) {
            float4 wa = wc4[j * 16];
            float4 wb = wc4[j * 16 + 1];
            float a = wa.x * fa.x + wa.y * fa.y + wa.z * fa.z + wa.w * fa.w
                    + wb.x * fb.x + wb.y * fb.y + wb.z * fb.z + wb.w * fb.w;
            s_part[j][g][q][ml] = a;
        }
    }
    __syncthreads();

    // ---- Reduce partials over channel groups: 16 warps <-> (j,q) --------
    {
        const int j = ww >> 1, qq = ww & 1;
        float s0 = 0.0f, s1 = 0.0f;
        #pragma unroll
        for (int gg = 0; gg < 8; gg++) {
            s0 += s_part[j][gg][qq][l];
            s1 += s_part[j][gg][qq][l + 32];
        }
        s_midf[j][qq][l]      = s0;
        s_midf[j][qq][l + 32] = s1;
    }
    __syncthreads();

    // ---- Expand + residual + contiguous float2 stores -------------------
    float mid0[8], mid1[8];
    #pragma unroll
    for (int j = 0; j < 8; j++) {
        mid0[j] = s_midf[j][0][ml];
        mid1[j] = s_midf[j][1][ml];
    }
    float* obp = out + ((size_t)(b * C_ + g * 8) * HHR_ + h) * WHR_ + 2 * m;
    #pragma unroll
    for (int i = 0; i < 8; i++) {
        const float4* we0 = (const float4*)&s_we[0][g * 8 + i][0];
        const float4* we1 = (const float4*)&s_we[1][g * 8 + i][0];
        float4 ea0 = we0[0], eb0 = we0[1];
        float4 ea1 = we1[0], eb1 = we1[1];
        float r0 = fea[0][i]
                 + ea0.x * mid0[0] + ea0.y * mid0[1] + ea0.z * mid0[2] + ea0.w * mid0[3]
                 + eb0.x * mid0[4] + eb0.y * mid0[5] + eb0.z * mid0[6] + eb0.w * mid0[7];
        float r1 = fea[1][i]
                 + ea1.x * mid1[0] + ea1.y * mid1[1] + ea1.z * mid1[2] + ea1.w * mid1[3]
                 + eb1.x * mid1[4] + eb1.y * mid1[5] + eb1.z * mid1[6] + eb1.w * mid1[7];
        float2 rv = make_float2(r0, r1);
        *(float2*)(obp + (size_t)i * HWHR_) = rv;
    }
}

// ---------------------------------------------------------------------------
extern "C" void kernel_launch(void* const* d_in, const int* in_sizes, int n_in,
                              void* d_out, int out_size)
{
    const float* fused = (const float*)d_in[1];
    const float* WC    = (const float*)d_in[2];
    const float* WE    = (const float*)d_in[3];
    const float* w1    = (const float*)d_in[4];
    const float* b1    = (const float*)d_in[5];
    const float* w2    = (const float*)d_in[6];
    const float* b2    = (const float*)d_in[7];
    const float* rw    = (const float*)d_in[8];
    const float* rb    = (const float*)d_in[9];
    const float* ow    = (const float*)d_in[10];
    const float* obv   = (const float*)d_in[11];
    float* out = (float*)d_out;

    precompute_kernel<<<1, 1024>>>(w1, b1, w2, b2, rw, rb, ow, obv, WC, WE);

    dim3 grid(WHR_ / 128, HHR_, B_);
    upsample_main<<<grid, 512>>>(fused, out);
}